// round 5
// baseline (speedup 1.0000x reference)
#include <cuda_runtime.h>
#include <cuda_bf16.h>
#include <cstdint>
#include <cstddef>

// ---------------------------------------------------------------------------
// TRecTransformer: linear-attention encoder/decoder.
// GEMMs: bf16 mma.sync m16n8k16, 3-term hi/lo split, pre-split bf16 operands,
// cp.async 2-stage pipeline, 2 CTAs/SM.
// ---------------------------------------------------------------------------

#define NTOK   16384
#define DMODEL 512
#define DFF    2048
#define LSEQ   4096
#define SCH    16

#define SZ ((size_t)NTOK * DMODEL)        // 8,388,608 elements

// ---- scratch layout (BYTE offsets) ----
#define B_H     ((size_t)0)
#define B_Z     (B_H   + SZ*4)
#define B_O     (B_Z   + SZ*4)
#define B_TMP   (B_O   + SZ*4)
#define B_Q     (B_TMP + SZ*4)
#define B_K     (B_Q   + SZ*4)
#define B_V     (B_K   + SZ*4)
#define B_PKV   (B_V   + SZ*4)
#define B_PKS   (B_PKV + (size_t)SCH*32*4096*4)
#define B_KVB   (B_PKS + (size_t)SCH*32*64*4)
#define B_KSB   (B_KVB + (size_t)32*4096*4)
// bf16 activation pairs
#define B_HH    (B_KSB + (size_t)32*64*4)
#define B_HL    (B_HH + SZ*2)
#define B_ZH    (B_HL + SZ*2)
#define B_ZL    (B_ZH + SZ*2)
#define B_OH    (B_ZL + SZ*2)
#define B_OL    (B_OH + SZ*2)
#define B_ATH   (B_OL + SZ*2)
#define B_ATL   (B_ATH + SZ*2)
#define B_FH    (B_ATL + SZ*2)
#define B_FL    (B_FH + SZ*8)             // NTOK*DFF bf16
// bf16 weight pairs (transposed to [N,K])
#define B_WHA   (B_FL  + SZ*8)            // 48 x 512x512 (enc,dec_self,dec_cross)
#define B_WLA   (B_WHA + (size_t)48*262144*2)
#define B_WHF1  (B_WLA + (size_t)48*262144*2)   // 8 x [2048,512]
#define B_WLF1  (B_WHF1 + (size_t)8*1048576*2)
#define B_WHF2  (B_WLF1 + (size_t)8*1048576*2)  // 8 x [512,2048]
#define B_WLF2  (B_WHF2 + (size_t)8*1048576*2)
#define TOTAL_B (B_WLF2 + (size_t)8*1048576*2)

__device__ __align__(1024) unsigned char g_scratch[TOTAL_B];

typedef __nv_bfloat16 bf16;

// ---------------------------------------------------------------------------
// helpers
// ---------------------------------------------------------------------------
__device__ __forceinline__ uint32_t smem_u32(const void* p) {
    uint32_t a;
    asm("{ .reg .u64 t; cvta.to.shared.u64 t, %1; cvt.u32.u64 %0, t; }" : "=r"(a) : "l"(p));
    return a;
}
__device__ __forceinline__ void ldsm4(uint32_t* r, uint32_t addr) {
    asm volatile("ldmatrix.sync.aligned.m8n8.x4.shared.b16 {%0,%1,%2,%3}, [%4];"
        : "=r"(r[0]), "=r"(r[1]), "=r"(r[2]), "=r"(r[3]) : "r"(addr));
}
__device__ __forceinline__ void mma_bf16(float* c, const uint32_t* a, const uint32_t* b) {
    asm volatile(
        "mma.sync.aligned.m16n8k16.row.col.f32.bf16.bf16.f32 "
        "{%0,%1,%2,%3}, {%4,%5,%6,%7}, {%8,%9}, {%0,%1,%2,%3};"
        : "+f"(c[0]), "+f"(c[1]), "+f"(c[2]), "+f"(c[3])
        : "r"(a[0]), "r"(a[1]), "r"(a[2]), "r"(a[3]), "r"(b[0]), "r"(b[1]));
}
__device__ __forceinline__ void cp16(uint32_t d, const void* s) {
    asm volatile("cp.async.cg.shared.global [%0], [%1], 16;" :: "r"(d), "l"(s));
}
__device__ __forceinline__ void cp_commit() { asm volatile("cp.async.commit_group;" ::: "memory"); }
__device__ __forceinline__ void cp_wait1()  { asm volatile("cp.async.wait_group 1;" ::: "memory"); }
__device__ __forceinline__ void cp_wait0()  { asm volatile("cp.async.wait_group 0;" ::: "memory"); }

__device__ __forceinline__ void split1(float v, bf16& h, bf16& l) {
    h = __float2bfloat16(v);
    l = __float2bfloat16(v - __bfloat162float(h));
}

// ---------------------------------------------------------------------------
// GEMM: C[M,N] = act(A[M,K] @ Wt[N,K]^T + bias). bf16 3-term split mma.sync.
// Operands pre-split in global (Ah/Al, Bh/Bl bf16). 128x128 tile, Kc=32,
// 256 threads, 2-stage cp.async pipeline, 2 CTAs/SM.
// ACT: 0 none, 1 relu, 2 phi=elu+1.  OUTBF: 0 -> fp32 C, 1 -> bf16 Ch/Cl.
// ---------------------------------------------------------------------------
#define ROWB 80
#define MATB 10240
#define STGB 40960
#define SMEM_DYN (2 * STGB)

template<int ACT, int OUTBF>
__global__ __launch_bounds__(256, 2) void gemm_tc(
    const bf16* __restrict__ Ah, const bf16* __restrict__ Al,
    const bf16* __restrict__ Bh, const bf16* __restrict__ Bl,
    const float* __restrict__ bias,
    float* __restrict__ C, bf16* __restrict__ Ch, bf16* __restrict__ Cl,
    int M, int N, int K)
{
    extern __shared__ char smc[];
    const uint32_t smB = smem_u32(smc);

    const int tid = threadIdx.x, lane = tid & 31, wid = tid >> 5;
    const int row0 = blockIdx.y * 128, col0 = blockIdx.x * 128;
    const int wm = wid & 1, wn = wid >> 1;       // 2 x 4 warp grid

    float acc[4][4][4];
    #pragma unroll
    for (int i = 0; i < 4; i++)
        #pragma unroll
        for (int j = 0; j < 4; j++)
            #pragma unroll
            for (int e = 0; e < 4; e++) acc[i][j][e] = 0.f;

    const uint32_t aoff = (uint32_t)((wm * 64 + (lane & 7) + ((lane >> 3) & 1) * 8) * ROWB
                                     + (lane >> 4) * 16);
    const uint32_t boff = (uint32_t)((wn * 32 + (lane >> 4) * 8 + (lane & 7)) * ROWB
                                     + ((lane >> 3) & 1) * 16);

    const int NC = K / 32;
    const int pr = tid >> 2;             // producer row within 64-row half
    const int pb = (tid & 3) * 16;       // byte offset within 64B row chunk

    auto loadst = [&](int c, int s) {
        const int k0 = c * 32;
        const uint32_t st = smB + (uint32_t)s * STGB;
        #pragma unroll
        for (int m = 0; m < 4; m++) {
            const bf16* g = (m == 0) ? Ah : (m == 1) ? Al : (m == 2) ? Bh : Bl;
            const int rb = (m < 2) ? row0 : col0;
            #pragma unroll
            for (int hf = 0; hf < 2; hf++) {
                const int r = hf * 64 + pr;
                cp16(st + m * MATB + r * ROWB + pb,
                     (const char*)(g + (size_t)(rb + r) * K + k0) + pb);
            }
        }
    };

    auto compute = [&](int s) {
        const uint32_t base = smB + (uint32_t)s * STGB;
        #pragma unroll
        for (int ks = 0; ks < 2; ks++) {
            uint32_t ah[4][4], al[4][4], bh[4][2], bl[4][2];
            #pragma unroll
            for (int mi = 0; mi < 4; mi++) {
                ldsm4(ah[mi], base + aoff + mi * 1280 + ks * 32);
                ldsm4(al[mi], base + MATB + aoff + mi * 1280 + ks * 32);
            }
            #pragma unroll
            for (int j = 0; j < 2; j++) {
                uint32_t t[4];
                ldsm4(t, base + 2 * MATB + boff + j * 1280 + ks * 32);
                bh[2 * j][0] = t[0]; bh[2 * j][1] = t[1];
                bh[2 * j + 1][0] = t[2]; bh[2 * j + 1][1] = t[3];
                ldsm4(t, base + 3 * MATB + boff + j * 1280 + ks * 32);
                bl[2 * j][0] = t[0]; bl[2 * j][1] = t[1];
                bl[2 * j + 1][0] = t[2]; bl[2 * j + 1][1] = t[3];
            }
            // term-major: dependent MMAs on same acc separated by 15 others
            #pragma unroll
            for (int mi = 0; mi < 4; mi++)
                #pragma unroll
                for (int ni = 0; ni < 4; ni++) mma_bf16(acc[mi][ni], ah[mi], bh[ni]);
            #pragma unroll
            for (int mi = 0; mi < 4; mi++)
                #pragma unroll
                for (int ni = 0; ni < 4; ni++) mma_bf16(acc[mi][ni], ah[mi], bl[ni]);
            #pragma unroll
            for (int mi = 0; mi < 4; mi++)
                #pragma unroll
                for (int ni = 0; ni < 4; ni++) mma_bf16(acc[mi][ni], al[mi], bh[ni]);
        }
    };

    loadst(0, 0); cp_commit();
    loadst(1, 1); cp_commit();
    for (int c = 0; c < NC; c++) {
        if (c + 1 < NC) cp_wait1(); else cp_wait0();
        __syncthreads();
        compute(c & 1);
        __syncthreads();
        if (c + 2 < NC) { loadst(c + 2, c & 1); cp_commit(); }
    }

    // epilogue
    const int gm0 = row0 + wm * 64;
    const int gn0 = col0 + wn * 32;
    #pragma unroll
    for (int ni = 0; ni < 4; ni++) {
        const int cn = gn0 + ni * 8 + (lane & 3) * 2;
        const float b0 = bias[cn], b1 = bias[cn + 1];
        #pragma unroll
        for (int mi = 0; mi < 4; mi++) {
            const int rm = gm0 + mi * 16 + (lane >> 2);
            float t0 = acc[mi][ni][0] + b0;
            float t1 = acc[mi][ni][1] + b1;
            float t2 = acc[mi][ni][2] + b0;
            float t3 = acc[mi][ni][3] + b1;
            if (ACT == 1) {
                t0 = fmaxf(t0, 0.f); t1 = fmaxf(t1, 0.f);
                t2 = fmaxf(t2, 0.f); t3 = fmaxf(t3, 0.f);
            }
            if (ACT == 2) {
                t0 = t0 > 0.f ? t0 + 1.f : __expf(t0);
                t1 = t1 > 0.f ? t1 + 1.f : __expf(t1);
                t2 = t2 > 0.f ? t2 + 1.f : __expf(t2);
                t3 = t3 > 0.f ? t3 + 1.f : __expf(t3);
            }
            if (OUTBF == 0) {
                float2 v0; v0.x = t0; v0.y = t1;
                float2 v1; v1.x = t2; v1.y = t3;
                *(float2*)&C[(size_t)rm * N + cn]       = v0;
                *(float2*)&C[(size_t)(rm + 8) * N + cn] = v1;
            } else {
                bf16 h0, l0, h1, l1;
                __nv_bfloat162 hp, lp;
                split1(t0, h0, l0); split1(t1, h1, l1);
                hp.x = h0; hp.y = h1; lp.x = l0; lp.y = l1;
                *(__nv_bfloat162*)&Ch[(size_t)rm * N + cn] = hp;
                *(__nv_bfloat162*)&Cl[(size_t)rm * N + cn] = lp;
                split1(t2, h0, l0); split1(t3, h1, l1);
                hp.x = h0; hp.y = h1; lp.x = l0; lp.y = l1;
                *(__nv_bfloat162*)&Ch[(size_t)(rm + 8) * N + cn] = hp;
                *(__nv_bfloat162*)&Cl[(size_t)(rm + 8) * N + cn] = lp;
            }
        }
    }
}

// ---------------------------------------------------------------------------
// fused weight transpose + bf16 split: W[K,N] fp32 -> Wh,Wl [N,K] bf16
// ---------------------------------------------------------------------------
__global__ __launch_bounds__(256) void transpose_split_w(
    const float* __restrict__ W, bf16* __restrict__ Wh, bf16* __restrict__ Wl,
    int K, int N)
{
    __shared__ float t[32][33];
    const size_t mo = (size_t)blockIdx.z * K * N;
    const float* Wm = W + mo;
    const int n0 = blockIdx.x * 32, k0 = blockIdx.y * 32;
    const int tx = threadIdx.x & 31, ty = threadIdx.x >> 5;
    #pragma unroll
    for (int i = 0; i < 32; i += 8)
        t[ty + i][tx] = Wm[(size_t)(k0 + ty + i) * N + n0 + tx];
    __syncthreads();
    #pragma unroll
    for (int i = 0; i < 32; i += 8) {
        const float v = t[tx][ty + i];
        bf16 h, l;
        split1(v, h, l);
        const size_t idx = mo + (size_t)(n0 + ty + i) * K + k0 + tx;
        Wh[idx] = h; Wl[idx] = l;
    }
}

// ---------------------------------------------------------------------------
// linear-attention kernels
// ---------------------------------------------------------------------------
__global__ __launch_bounds__(256) void kv_partial(
    const float* __restrict__ Kt, const float* __restrict__ Vt,
    float* __restrict__ pkv, float* __restrict__ pks)
{
    const int bh = blockIdx.x, ch = blockIdx.y;
    const int b = bh >> 3, h = bh & 7;
    const int tid = threadIdx.x;
    __shared__ float Ks[4][64], Vs[4][64];

    float acc[16];
    #pragma unroll
    for (int j = 0; j < 16; j++) acc[j] = 0.f;
    float ksa = 0.f;

    const int s0 = ch * (LSEQ / SCH);
    const size_t base = ((size_t)b * LSEQ) * DMODEL + h * 64;
    const int r = tid >> 6, d = tid & 63;

    for (int s = s0; s < s0 + LSEQ / SCH; s += 4) {
        const size_t off = base + (size_t)(s + r) * DMODEL + d;
        Ks[r][d] = Kt[off];
        Vs[r][d] = Vt[off];
        __syncthreads();
        #pragma unroll
        for (int rr = 0; rr < 4; rr++) {
            #pragma unroll
            for (int j = 0; j < 16; j++) {
                const int flat = j * 256 + tid;
                acc[j] = fmaf(Ks[rr][flat >> 6], Vs[rr][flat & 63], acc[j]);
            }
            if (tid < 64) ksa += Ks[rr][tid];
        }
        __syncthreads();
    }
    float* o = pkv + ((size_t)ch * 32 + bh) * 4096;
    #pragma unroll
    for (int j = 0; j < 16; j++) o[j * 256 + tid] = acc[j];
    if (tid < 64) pks[((size_t)ch * 32 + bh) * 64 + tid] = ksa;
}

__global__ __launch_bounds__(256) void kv_reduce(
    const float* __restrict__ pkv, const float* __restrict__ pks,
    float* __restrict__ kv, float* __restrict__ ks)
{
    const int bh = blockIdx.x, tid = threadIdx.x;
    for (int e = tid; e < 4096; e += 256) {
        float s = 0.f;
        #pragma unroll
        for (int c = 0; c < SCH; c++) s += pkv[((size_t)c * 32 + bh) * 4096 + e];
        kv[(size_t)bh * 4096 + e] = s;
    }
    if (tid < 64) {
        float s = 0.f;
        #pragma unroll
        for (int c = 0; c < SCH; c++) s += pks[((size_t)c * 32 + bh) * 64 + tid];
        ks[bh * 64 + tid] = s;
    }
}

__global__ __launch_bounds__(256) void attn_out(
    const float* __restrict__ Q, const float* __restrict__ kv,
    const float* __restrict__ ksum,
    bf16* __restrict__ Oh, bf16* __restrict__ Ol)
{
    const int bh = blockIdx.x, b = bh >> 3, h = bh & 7;
    __shared__ float kvs[64][64];
    __shared__ float kss[64];
    const int tid = threadIdx.x;
    for (int e = tid; e < 4096; e += 256) kvs[e >> 6][e & 63] = kv[(size_t)bh * 4096 + e];
    if (tid < 64) kss[tid] = ksum[bh * 64 + tid];
    __syncthreads();

    const int warp = tid >> 5, lane = tid & 31;
    const int tpb = LSEQ / gridDim.y;
    const int l0 = blockIdx.y * tpb;

    for (int l = l0 + warp; l < l0 + tpb; l += 8) {
        const float* q = Q + ((size_t)(b * LSEQ + l)) * DMODEL + h * 64;
        const float q0 = q[lane], q1 = q[lane + 32];
        float zd = q0 * kss[lane] + q1 * kss[lane + 32];
        #pragma unroll
        for (int o = 16; o > 0; o >>= 1) zd += __shfl_xor_sync(0xffffffffu, zd, o);
        const float z = 1.f / (zd + 1e-6f);

        float a0 = 0.f, a1 = 0.f;
        #pragma unroll
        for (int dd = 0; dd < 32; dd++) {
            const float qd = __shfl_sync(0xffffffffu, q0, dd);
            a0 = fmaf(qd, kvs[dd][lane],      a0);
            a1 = fmaf(qd, kvs[dd][lane + 32], a1);
        }
        #pragma unroll
        for (int dd = 0; dd < 32; dd++) {
            const float qd = __shfl_sync(0xffffffffu, q1, dd);
            a0 = fmaf(qd, kvs[dd + 32][lane],      a0);
            a1 = fmaf(qd, kvs[dd + 32][lane + 32], a1);
        }
        const size_t op = ((size_t)(b * LSEQ + l)) * DMODEL + h * 64;
        bf16 hh, ll;
        split1(a0 * z, hh, ll); Oh[op + lane] = hh;      Ol[op + lane] = ll;
        split1(a1 * z, hh, ll); Oh[op + lane + 32] = hh; Ol[op + lane + 32] = ll;
    }
}

__global__ __launch_bounds__(128) void ln_kernel(
    const float* __restrict__ X, const float* __restrict__ R,
    const float* __restrict__ gb, float* __restrict__ Y,
    bf16* __restrict__ Yh, bf16* __restrict__ Yl)
{
    const int t = blockIdx.x, tid = threadIdx.x;
    const float* x = X + (size_t)t * DMODEL;
    float v[4];
    float s = 0.f;
    #pragma unroll
    for (int i = 0; i < 4; i++) {
        float val = x[tid + i * 128];
        if (R) val += R[(size_t)t * DMODEL + tid + i * 128];
        v[i] = val; s += val;
    }
    __shared__ float red[4];
    #pragma unroll
    for (int o = 16; o > 0; o >>= 1) s += __shfl_xor_sync(0xffffffffu, s, o);
    if ((tid & 31) == 0) red[tid >> 5] = s;
    __syncthreads();
    const float mu = (red[0] + red[1] + red[2] + red[3]) * (1.f / DMODEL);
    float qq = 0.f;
    #pragma unroll
    for (int i = 0; i < 4; i++) { const float dd = v[i] - mu; qq += dd * dd; }
    #pragma unroll
    for (int o = 16; o > 0; o >>= 1) qq += __shfl_xor_sync(0xffffffffu, qq, o);
    __syncthreads();
    if ((tid & 31) == 0) red[tid >> 5] = qq;
    __syncthreads();
    const float var = (red[0] + red[1] + red[2] + red[3]) * (1.f / DMODEL);
    const float rstd = rsqrtf(var + 1e-5f);
    #pragma unroll
    for (int i = 0; i < 4; i++) {
        const int j = tid + i * 128;
        const float out = (v[i] - mu) * rstd * gb[j] + gb[DMODEL + j];
        Y[(size_t)t * DMODEL + j] = out;
        if (Yh) {
            bf16 h, l;
            split1(out, h, l);
            Yh[(size_t)t * DMODEL + j] = h;
            Yl[(size_t)t * DMODEL + j] = l;
        }
    }
}

__global__ void embed_kernel(
    const float* __restrict__ x, const float* __restrict__ pe,
    const float* __restrict__ ew, const float* __restrict__ eb,
    float* __restrict__ h, bf16* __restrict__ hh, bf16* __restrict__ hl)
{
    const size_t idx = (size_t)blockIdx.x * blockDim.x + threadIdx.x;
    const int tok = (int)(idx >> 9);
    const int j   = (int)(idx & 511);
    const int l   = tok & (LSEQ - 1);
    float val;
    if (j < 256) val = x[(size_t)tok * 2] * ew[j] + x[(size_t)tok * 2 + 1] * ew[256 + j] + eb[j];
    else         val = pe[(size_t)l * 256 + (j - 256)];
    h[idx] = val;
    bf16 vh, vl;
    split1(val, vh, vl);
    hh[idx] = vh; hl[idx] = vl;
}

__global__ void dec_init_kernel(const float* __restrict__ ope, float* __restrict__ o,
                                bf16* __restrict__ oh, bf16* __restrict__ ol)
{
    const size_t idx = (size_t)blockIdx.x * blockDim.x + threadIdx.x;
    const size_t tok = idx >> 9;
    const float val = ope[((tok & (LSEQ - 1)) << 9) | (idx & 511)];
    o[idx] = val;
    bf16 vh, vl;
    split1(val, vh, vl);
    oh[idx] = vh; ol[idx] = vl;
}

__global__ void pred_kernel(
    const float* __restrict__ Xf, const float* __restrict__ pw,
    const float* __restrict__ pb, float* __restrict__ out)
{
    const int gw = (int)(((size_t)blockIdx.x * blockDim.x + threadIdx.x) >> 5);
    const int lane = threadIdx.x & 31;
    if (gw >= NTOK) return;
    const float* xr = Xf + (size_t)gw * DMODEL;
    float a0 = 0.f, a1 = 0.f;
    #pragma unroll 4
    for (int j = lane; j < DMODEL; j += 32) {
        const float v = xr[j];
        a0 = fmaf(v, pw[2 * j],     a0);
        a1 = fmaf(v, pw[2 * j + 1], a1);
    }
    #pragma unroll
    for (int o = 16; o > 0; o >>= 1) {
        a0 += __shfl_xor_sync(0xffffffffu, a0, o);
        a1 += __shfl_xor_sync(0xffffffffu, a1, o);
    }
    if (lane == 0) { out[2 * gw] = a0 + pb[0]; out[2 * gw + 1] = a1 + pb[1]; }
}

// ---------------------------------------------------------------------------
// Host orchestration
// ---------------------------------------------------------------------------
struct Ptrs {
    float *h, *z, *o, *tmp, *q, *k, *v, *pkv, *pks, *kv, *ks;
    bf16 *hh, *hl, *zh, *zl, *oh, *ol, *ath, *atl, *fh, *fl;
    bf16 *wha, *wla, *whf1, *wlf1, *whf2, *wlf2;
};

static void gemm20(const bf16* ah, const bf16* al, const bf16* bh, const bf16* bl,
                   const float* bias, float* C, int M, int N, int K) {
    gemm_tc<2,0><<<dim3(N/128, M/128), 256, SMEM_DYN>>>(ah, al, bh, bl, bias, C, nullptr, nullptr, M, N, K);
}
static void gemm00(const bf16* ah, const bf16* al, const bf16* bh, const bf16* bl,
                   const float* bias, float* C, int M, int N, int K) {
    gemm_tc<0,0><<<dim3(N/128, M/128), 256, SMEM_DYN>>>(ah, al, bh, bl, bias, C, nullptr, nullptr, M, N, K);
}
static void gemm11(const bf16* ah, const bf16* al, const bf16* bh, const bf16* bl,
                   const float* bias, bf16* Ch, bf16* Cl, int M, int N, int K) {
    gemm_tc<1,1><<<dim3(N/128, M/128), 256, SMEM_DYN>>>(ah, al, bh, bl, bias, nullptr, Ch, Cl, M, N, K);
}

static void attention_block(const bf16* xqh, const bf16* xql,
                            const bf16* xkh, const bf16* xkl,
                            const bf16* wh, const bf16* wl,
                            const float* b, const Ptrs& P)
{
    const size_t WS = (size_t)DMODEL * DMODEL;
    gemm20(xqh, xql, wh + 0 * WS, wl + 0 * WS, b + 0 * DMODEL, P.q, NTOK, DMODEL, DMODEL);
    gemm20(xkh, xkl, wh + 1 * WS, wl + 1 * WS, b + 1 * DMODEL, P.k, NTOK, DMODEL, DMODEL);
    gemm00(xkh, xkl, wh + 2 * WS, wl + 2 * WS, b + 2 * DMODEL, P.v, NTOK, DMODEL, DMODEL);

    kv_partial<<<dim3(32, SCH), 256>>>(P.k, P.v, P.pkv, P.pks);
    kv_reduce<<<32, 256>>>(P.pkv, P.pks, P.kv, P.ks);
    attn_out<<<dim3(32, 32), 256>>>(P.q, P.kv, P.ks, P.ath, P.atl);

    gemm00(P.ath, P.atl, wh + 3 * WS, wl + 3 * WS, b + 3 * DMODEL, P.tmp, NTOK, DMODEL, DMODEL);
}

extern "C" void kernel_launch(void* const* d_in, const int* in_sizes, int n_in,
                              void* d_out, int out_size)
{
    const float* x            = (const float*)d_in[0];
    const float* out_pos_emb  = (const float*)d_in[1];
    const float* pe_input     = (const float*)d_in[2];
    const float* emb_w        = (const float*)d_in[3];
    const float* emb_b        = (const float*)d_in[4];
    const float* enc_attn_w   = (const float*)d_in[5];
    const float* enc_attn_b   = (const float*)d_in[6];
    const float* enc_ln       = (const float*)d_in[7];
    const float* enc_ff_w1    = (const float*)d_in[8];
    const float* enc_ff_b1    = (const float*)d_in[9];
    const float* enc_ff_w2    = (const float*)d_in[10];
    const float* enc_ff_b2    = (const float*)d_in[11];
    const float* enc_final_ln = (const float*)d_in[12];
    const float* dec_self_w   = (const float*)d_in[13];
    const float* dec_self_b   = (const float*)d_in[14];
    const float* dec_cross_w  = (const float*)d_in[15];
    const float* dec_cross_b  = (const float*)d_in[16];
    const float* dec_ln       = (const float*)d_in[17];
    const float* dec_ff_w1    = (const float*)d_in[18];
    const float* dec_ff_b1    = (const float*)d_in[19];
    const float* dec_ff_w2    = (const float*)d_in[20];
    const float* dec_ff_b2    = (const float*)d_in[21];
    const float* dec_final_ln = (const float*)d_in[22];
    const float* pred_w       = (const float*)d_in[23];
    const float* pred_b       = (const float*)d_in[24];

    cudaFuncSetAttribute(gemm_tc<2,0>, cudaFuncAttributeMaxDynamicSharedMemorySize, SMEM_DYN);
    cudaFuncSetAttribute(gemm_tc<0,0>, cudaFuncAttributeMaxDynamicSharedMemorySize, SMEM_DYN);
    cudaFuncSetAttribute(gemm_tc<1,1>, cudaFuncAttributeMaxDynamicSharedMemorySize, SMEM_DYN);

    unsigned char* S = nullptr;
    cudaGetSymbolAddress((void**)&S, g_scratch);

    Ptrs P;
    P.h   = (float*)(S + B_H);   P.z   = (float*)(S + B_Z);   P.o  = (float*)(S + B_O);
    P.tmp = (float*)(S + B_TMP); P.q   = (float*)(S + B_Q);   P.k  = (float*)(S + B_K);
    P.v   = (float*)(S + B_V);   P.pkv = (float*)(S + B_PKV); P.pks = (float*)(S + B_PKS);
    P.kv  = (float*)(S + B_KVB); P.ks  = (float*)(S + B_KSB);
    P.hh  = (bf16*)(S + B_HH);   P.hl  = (bf16*)(S + B_HL);
    P.zh  = (bf16*)(S + B_ZH);   P.zl  = (bf16*)(S + B_ZL);
    P.oh  = (bf16*)(S + B_OH);   P.ol  = (bf16*)(S + B_OL);
    P.ath = (bf16*)(S + B_ATH);  P.atl = (bf16*)(S + B_ATL);
    P.fh  = (bf16*)(S + B_FH);   P.fl  = (bf16*)(S + B_FL);
    P.wha = (bf16*)(S + B_WHA);  P.wla = (bf16*)(S + B_WLA);
    P.whf1 = (bf16*)(S + B_WHF1); P.wlf1 = (bf16*)(S + B_WLF1);
    P.whf2 = (bf16*)(S + B_WHF2); P.wlf2 = (bf16*)(S + B_WLF2);

    // ---- transpose + split all weights ----
    transpose_split_w<<<dim3(16, 16, 16), 256>>>(enc_attn_w,  P.wha,                P.wla,                512, 512);
    transpose_split_w<<<dim3(16, 16, 16), 256>>>(dec_self_w,  P.wha + (size_t)16*262144, P.wla + (size_t)16*262144, 512, 512);
    transpose_split_w<<<dim3(16, 16, 16), 256>>>(dec_cross_w, P.wha + (size_t)32*262144, P.wla + (size_t)32*262144, 512, 512);
    transpose_split_w<<<dim3(64, 16, 4),  256>>>(enc_ff_w1, P.whf1,                      P.wlf1,                      512, 2048);
    transpose_split_w<<<dim3(64, 16, 4),  256>>>(dec_ff_w1, P.whf1 + (size_t)4*1048576, P.wlf1 + (size_t)4*1048576, 512, 2048);
    transpose_split_w<<<dim3(16, 64, 4),  256>>>(enc_ff_w2, P.whf2,                      P.wlf2,                      2048, 512);
    transpose_split_w<<<dim3(16, 64, 4),  256>>>(dec_ff_w2, P.whf2 + (size_t)4*1048576, P.wlf2 + (size_t)4*1048576, 2048, 512);

    const size_t WT4 = (size_t)4 * DMODEL * DMODEL;
    const size_t W1S = (size_t)DFF * DMODEL;
    const size_t W2S = (size_t)DMODEL * DFF;

    // ---- embed ----
    embed_kernel<<<(NTOK * DMODEL) / 256, 256>>>(x, pe_input, emb_w, emb_b, P.h, P.hh, P.hl);

    // ---- encoder ----
    for (int l = 0; l < 4; l++) {
        const float* ln = enc_ln + (size_t)l * 2 * 2 * DMODEL;
        attention_block(P.hh, P.hl, P.hh, P.hl,
                        P.wha + (size_t)l * WT4, P.wla + (size_t)l * WT4,
                        enc_attn_b + (size_t)l * 4 * DMODEL, P);
        ln_kernel<<<NTOK, 128>>>(P.h, P.tmp, ln, P.h, P.hh, P.hl);
        gemm11(P.hh, P.hl, P.whf1 + (size_t)l * W1S, P.wlf1 + (size_t)l * W1S,
               enc_ff_b1 + (size_t)l * DFF, P.fh, P.fl, NTOK, DFF, DMODEL);
        gemm00(P.fh, P.fl, P.whf2 + (size_t)l * W2S, P.wlf2 + (size_t)l * W2S,
               enc_ff_b2 + (size_t)l * DMODEL, P.tmp, NTOK, DMODEL, DFF);
        ln_kernel<<<NTOK, 128>>>(P.h, P.tmp, ln + 2 * DMODEL, P.h, P.hh, P.hl);
    }
    ln_kernel<<<NTOK, 128>>>(P.h, nullptr, enc_final_ln, P.z, P.zh, P.zl);

    // ---- decoder ----
    dec_init_kernel<<<(NTOK * DMODEL) / 256, 256>>>(out_pos_emb, P.o, P.oh, P.ol);
    for (int l = 0; l < 4; l++) {
        const float* ln = dec_ln + (size_t)l * 3 * 2 * DMODEL;
        attention_block(P.oh, P.ol, P.oh, P.ol,
                        P.wha + (size_t)(16 + l * 4) * DMODEL * DMODEL,
                        P.wla + (size_t)(16 + l * 4) * DMODEL * DMODEL,
                        dec_self_b + (size_t)l * 4 * DMODEL, P);
        ln_kernel<<<NTOK, 128>>>(P.o, P.tmp, ln, P.o, P.oh, P.ol);
        attention_block(P.oh, P.ol, P.zh, P.zl,
                        P.wha + (size_t)(32 + l * 4) * DMODEL * DMODEL,
                        P.wla + (size_t)(32 + l * 4) * DMODEL * DMODEL,
                        dec_cross_b + (size_t)l * 4 * DMODEL, P);
        ln_kernel<<<NTOK, 128>>>(P.o, P.tmp, ln + 2 * DMODEL, P.o, P.oh, P.ol);
        gemm11(P.oh, P.ol, P.whf1 + (size_t)(4 + l) * W1S, P.wlf1 + (size_t)(4 + l) * W1S,
               dec_ff_b1 + (size_t)l * DFF, P.fh, P.fl, NTOK, DFF, DMODEL);
        gemm00(P.fh, P.fl, P.whf2 + (size_t)(4 + l) * W2S, P.wlf2 + (size_t)(4 + l) * W2S,
               dec_ff_b2 + (size_t)l * DMODEL, P.tmp, NTOK, DMODEL, DFF);
        ln_kernel<<<NTOK, 128>>>(P.o, P.tmp, ln + 4 * DMODEL, P.o, P.oh, P.ol);
    }
    ln_kernel<<<NTOK, 128>>>(P.o, nullptr, dec_final_ln, P.tmp, nullptr, nullptr);

    // ---- prediction head ----
    pred_kernel<<<(NTOK * 32) / 256, 256>>>(P.tmp, pred_w, pred_b, (float*)d_out);
}

// round 6
// speedup vs baseline: 1.4702x; 1.4702x over previous
#include <cuda_runtime.h>
#include <cuda_fp16.h>
#include <cstdint>
#include <cstddef>

// ---------------------------------------------------------------------------
// TRecTransformer: linear-attention encoder/decoder.
// GEMMs: fp16 mma.sync m16n8k16, 2-term split (A single fp16, W = Wh + Wl),
// cp.async 3-stage pipeline.
// ---------------------------------------------------------------------------

#define NTOK   16384
#define DMODEL 512
#define DFF    2048
#define LSEQ   4096
#define SCH    16

#define SZ ((size_t)NTOK * DMODEL)        // 8,388,608 elements

// ---- scratch layout (BYTE offsets) ----
#define B_H     ((size_t)0)
#define B_Z     (B_H   + SZ*4)
#define B_O     (B_Z   + SZ*4)
#define B_TMP   (B_O   + SZ*4)
#define B_Q     (B_TMP + SZ*4)
#define B_K     (B_Q   + SZ*4)
#define B_V     (B_K   + SZ*4)
#define B_PKV   (B_V   + SZ*4)
#define B_PKS   (B_PKV + (size_t)SCH*32*4096*4)
#define B_KVB   (B_PKS + (size_t)SCH*32*64*4)
#define B_KSB   (B_KVB + (size_t)32*4096*4)
// fp16 activations (single-rounded)
#define B_HH    (B_KSB + (size_t)32*64*4)
#define B_ZH    (B_HH  + SZ*2)
#define B_OH    (B_ZH  + SZ*2)
#define B_ATH   (B_OH  + SZ*2)
#define B_FH    (B_ATH + SZ*2)            // NTOK*DFF halves
// fp16 weight hi/lo pairs (transposed to [N,K])
#define B_WHA   (B_FH  + SZ*8)            // 48 x 512x512
#define B_WLA   (B_WHA + (size_t)48*262144*2)
#define B_WHF1  (B_WLA + (size_t)48*262144*2)   // 8 x [2048,512]
#define B_WLF1  (B_WHF1 + (size_t)8*1048576*2)
#define B_WHF2  (B_WLF1 + (size_t)8*1048576*2)  // 8 x [512,2048]
#define B_WLF2  (B_WHF2 + (size_t)8*1048576*2)
#define TOTAL_B (B_WLF2 + (size_t)8*1048576*2)

__device__ __align__(1024) unsigned char g_scratch[TOTAL_B];

typedef __half fp16;

// ---------------------------------------------------------------------------
// helpers
// ---------------------------------------------------------------------------
__device__ __forceinline__ uint32_t smem_u32(const void* p) {
    uint32_t a;
    asm("{ .reg .u64 t; cvta.to.shared.u64 t, %1; cvt.u32.u64 %0, t; }" : "=r"(a) : "l"(p));
    return a;
}
__device__ __forceinline__ void ldsm4(uint32_t* r, uint32_t addr) {
    asm volatile("ldmatrix.sync.aligned.m8n8.x4.shared.b16 {%0,%1,%2,%3}, [%4];"
        : "=r"(r[0]), "=r"(r[1]), "=r"(r[2]), "=r"(r[3]) : "r"(addr));
}
__device__ __forceinline__ void mma_f16(float* c, const uint32_t* a, const uint32_t* b) {
    asm volatile(
        "mma.sync.aligned.m16n8k16.row.col.f32.f16.f16.f32 "
        "{%0,%1,%2,%3}, {%4,%5,%6,%7}, {%8,%9}, {%0,%1,%2,%3};"
        : "+f"(c[0]), "+f"(c[1]), "+f"(c[2]), "+f"(c[3])
        : "r"(a[0]), "r"(a[1]), "r"(a[2]), "r"(a[3]), "r"(b[0]), "r"(b[1]));
}
__device__ __forceinline__ void cp16(uint32_t d, const void* s) {
    asm volatile("cp.async.cg.shared.global [%0], [%1], 16;" :: "r"(d), "l"(s));
}
__device__ __forceinline__ void cp_commit() { asm volatile("cp.async.commit_group;" ::: "memory"); }
__device__ __forceinline__ void cp_wait1()  { asm volatile("cp.async.wait_group 1;" ::: "memory"); }
__device__ __forceinline__ void cp_wait0()  { asm volatile("cp.async.wait_group 0;" ::: "memory"); }

__device__ __forceinline__ void split1h(float v, fp16& h, fp16& l) {
    h = __float2half_rn(v);
    l = __float2half_rn(v - __half2float(h));
}

// ---------------------------------------------------------------------------
// GEMM: C[M,N] = act(A[M,K] @ (Wh+Wl)[N,K]^T + bias). fp16 2-term mma.sync.
// A single fp16, W split hi/lo. 128x128 tile, Kc=32, 256 threads,
// 3-stage cp.async pipeline, 3 smem matrices per stage.
// ACT: 0 none, 1 relu, 2 phi=elu+1.  OUTBF: 0 -> fp32 C, 1 -> fp16 Ch.
// ---------------------------------------------------------------------------
#define ROWB 80
#define MATB 10240
#define STGB 30720
#define SMEM_DYN (3 * STGB)

template<int ACT, int OUTBF>
__global__ __launch_bounds__(256) void gemm_tc(
    const fp16* __restrict__ A,
    const fp16* __restrict__ Bh, const fp16* __restrict__ Bl,
    const float* __restrict__ bias,
    float* __restrict__ C, fp16* __restrict__ Ch,
    int M, int N, int K)
{
    extern __shared__ char smc[];
    const uint32_t smB = smem_u32(smc);

    const int tid = threadIdx.x, lane = tid & 31, wid = tid >> 5;
    const int row0 = blockIdx.y * 128, col0 = blockIdx.x * 128;
    const int wm = wid & 1, wn = wid >> 1;       // 2 x 4 warp grid

    float acc[4][4][4];
    #pragma unroll
    for (int i = 0; i < 4; i++)
        #pragma unroll
        for (int j = 0; j < 4; j++)
            #pragma unroll
            for (int e = 0; e < 4; e++) acc[i][j][e] = 0.f;

    const uint32_t aoff = (uint32_t)((wm * 64 + (lane & 7) + ((lane >> 3) & 1) * 8) * ROWB
                                     + (lane >> 4) * 16);
    const uint32_t boff = (uint32_t)((wn * 32 + (lane >> 4) * 8 + (lane & 7)) * ROWB
                                     + ((lane >> 3) & 1) * 16);

    const int NC = K / 32;
    const int pr = tid >> 2;             // producer row within 64-row half
    const int pb = (tid & 3) * 16;       // byte offset within 64B row chunk

    auto loadst = [&](int c, int s) {
        const int k0 = c * 32;
        const uint32_t st = smB + (uint32_t)s * STGB;
        #pragma unroll
        for (int m = 0; m < 3; m++) {
            const fp16* g = (m == 0) ? A : (m == 1) ? Bh : Bl;
            const int rb = (m == 0) ? row0 : col0;
            #pragma unroll
            for (int hf = 0; hf < 2; hf++) {
                const int r = hf * 64 + pr;
                cp16(st + m * MATB + r * ROWB + pb,
                     (const char*)(g + (size_t)(rb + r) * K + k0) + pb);
            }
        }
    };

    auto compute = [&](int s) {
        const uint32_t base = smB + (uint32_t)s * STGB;
        #pragma unroll
        for (int ks = 0; ks < 2; ks++) {
            uint32_t ar[4][4], bh[4][2], bl[4][2];
            #pragma unroll
            for (int mi = 0; mi < 4; mi++)
                ldsm4(ar[mi], base + aoff + mi * 1280 + ks * 32);
            #pragma unroll
            for (int j = 0; j < 2; j++) {
                uint32_t t[4];
                ldsm4(t, base + MATB + boff + j * 1280 + ks * 32);
                bh[2 * j][0] = t[0]; bh[2 * j][1] = t[1];
                bh[2 * j + 1][0] = t[2]; bh[2 * j + 1][1] = t[3];
                ldsm4(t, base + 2 * MATB + boff + j * 1280 + ks * 32);
                bl[2 * j][0] = t[0]; bl[2 * j][1] = t[1];
                bl[2 * j + 1][0] = t[2]; bl[2 * j + 1][1] = t[3];
            }
            // term-major: dependent MMAs on same acc separated by 15 others
            #pragma unroll
            for (int mi = 0; mi < 4; mi++)
                #pragma unroll
                for (int ni = 0; ni < 4; ni++) mma_f16(acc[mi][ni], ar[mi], bh[ni]);
            #pragma unroll
            for (int mi = 0; mi < 4; mi++)
                #pragma unroll
                for (int ni = 0; ni < 4; ni++) mma_f16(acc[mi][ni], ar[mi], bl[ni]);
        }
    };

    loadst(0, 0); cp_commit();
    loadst(1, 1); cp_commit();
    for (int c = 0; c < NC; c++) {
        if (c + 1 < NC) cp_wait1(); else cp_wait0();
        __syncthreads();
        compute(c % 3);
        if (c + 2 < NC) { loadst(c + 2, (c + 2) % 3); cp_commit(); }
    }

    // epilogue
    const int gm0 = row0 + wm * 64;
    const int gn0 = col0 + wn * 32;
    #pragma unroll
    for (int ni = 0; ni < 4; ni++) {
        const int cn = gn0 + ni * 8 + (lane & 3) * 2;
        const float b0 = bias[cn], b1 = bias[cn + 1];
        #pragma unroll
        for (int mi = 0; mi < 4; mi++) {
            const int rm = gm0 + mi * 16 + (lane >> 2);
            float t0 = acc[mi][ni][0] + b0;
            float t1 = acc[mi][ni][1] + b1;
            float t2 = acc[mi][ni][2] + b0;
            float t3 = acc[mi][ni][3] + b1;
            if (ACT == 1) {
                t0 = fmaxf(t0, 0.f); t1 = fmaxf(t1, 0.f);
                t2 = fmaxf(t2, 0.f); t3 = fmaxf(t3, 0.f);
            }
            if (ACT == 2) {
                t0 = t0 > 0.f ? t0 + 1.f : __expf(t0);
                t1 = t1 > 0.f ? t1 + 1.f : __expf(t1);
                t2 = t2 > 0.f ? t2 + 1.f : __expf(t2);
                t3 = t3 > 0.f ? t3 + 1.f : __expf(t3);
            }
            if (OUTBF == 0) {
                float2 v0; v0.x = t0; v0.y = t1;
                float2 v1; v1.x = t2; v1.y = t3;
                *(float2*)&C[(size_t)rm * N + cn]       = v0;
                *(float2*)&C[(size_t)(rm + 8) * N + cn] = v1;
            } else {
                __half2 hp;
                hp.x = __float2half_rn(t0); hp.y = __float2half_rn(t1);
                *(__half2*)&Ch[(size_t)rm * N + cn] = hp;
                hp.x = __float2half_rn(t2); hp.y = __float2half_rn(t3);
                *(__half2*)&Ch[(size_t)(rm + 8) * N + cn] = hp;
            }
        }
    }
}

// ---------------------------------------------------------------------------
// fused weight transpose + fp16 split: W[K,N] fp32 -> Wh,Wl [N,K] fp16
// ---------------------------------------------------------------------------
__global__ __launch_bounds__(256) void transpose_split_w(
    const float* __restrict__ W, fp16* __restrict__ Wh, fp16* __restrict__ Wl,
    int K, int N)
{
    __shared__ float t[32][33];
    const size_t mo = (size_t)blockIdx.z * K * N;
    const float* Wm = W + mo;
    const int n0 = blockIdx.x * 32, k0 = blockIdx.y * 32;
    const int tx = threadIdx.x & 31, ty = threadIdx.x >> 5;
    #pragma unroll
    for (int i = 0; i < 32; i += 8)
        t[ty + i][tx] = Wm[(size_t)(k0 + ty + i) * N + n0 + tx];
    __syncthreads();
    #pragma unroll
    for (int i = 0; i < 32; i += 8) {
        const float v = t[tx][ty + i];
        fp16 h, l;
        split1h(v, h, l);
        const size_t idx = mo + (size_t)(n0 + ty + i) * K + k0 + tx;
        Wh[idx] = h; Wl[idx] = l;
    }
}

// ---------------------------------------------------------------------------
// linear-attention kernels
// ---------------------------------------------------------------------------
__global__ __launch_bounds__(256) void kv_partial(
    const float* __restrict__ Kt, const float* __restrict__ Vt,
    float* __restrict__ pkv, float* __restrict__ pks)
{
    const int bh = blockIdx.x, ch = blockIdx.y;
    const int b = bh >> 3, h = bh & 7;
    const int tid = threadIdx.x;
    __shared__ float Ks[4][64], Vs[4][64];

    float acc[16];
    #pragma unroll
    for (int j = 0; j < 16; j++) acc[j] = 0.f;
    float ksa = 0.f;

    const int s0 = ch * (LSEQ / SCH);
    const size_t base = ((size_t)b * LSEQ) * DMODEL + h * 64;
    const int r = tid >> 6, d = tid & 63;

    for (int s = s0; s < s0 + LSEQ / SCH; s += 4) {
        const size_t off = base + (size_t)(s + r) * DMODEL + d;
        Ks[r][d] = Kt[off];
        Vs[r][d] = Vt[off];
        __syncthreads();
        #pragma unroll
        for (int rr = 0; rr < 4; rr++) {
            #pragma unroll
            for (int j = 0; j < 16; j++) {
                const int flat = j * 256 + tid;
                acc[j] = fmaf(Ks[rr][flat >> 6], Vs[rr][flat & 63], acc[j]);
            }
            if (tid < 64) ksa += Ks[rr][tid];
        }
        __syncthreads();
    }
    float* o = pkv + ((size_t)ch * 32 + bh) * 4096;
    #pragma unroll
    for (int j = 0; j < 16; j++) o[j * 256 + tid] = acc[j];
    if (tid < 64) pks[((size_t)ch * 32 + bh) * 64 + tid] = ksa;
}

__global__ __launch_bounds__(256) void kv_reduce(
    const float* __restrict__ pkv, const float* __restrict__ pks,
    float* __restrict__ kv, float* __restrict__ ks)
{
    const int bh = blockIdx.x, tid = threadIdx.x;
    for (int e = tid; e < 4096; e += 256) {
        float s = 0.f;
        #pragma unroll
        for (int c = 0; c < SCH; c++) s += pkv[((size_t)c * 32 + bh) * 4096 + e];
        kv[(size_t)bh * 4096 + e] = s;
    }
    if (tid < 64) {
        float s = 0.f;
        #pragma unroll
        for (int c = 0; c < SCH; c++) s += pks[((size_t)c * 32 + bh) * 64 + tid];
        ks[bh * 64 + tid] = s;
    }
}

__global__ __launch_bounds__(256) void attn_out(
    const float* __restrict__ Q, const float* __restrict__ kv,
    const float* __restrict__ ksum, fp16* __restrict__ Oh)
{
    const int bh = blockIdx.x, b = bh >> 3, h = bh & 7;
    __shared__ float kvs[64][64];
    __shared__ float kss[64];
    const int tid = threadIdx.x;
    for (int e = tid; e < 4096; e += 256) kvs[e >> 6][e & 63] = kv[(size_t)bh * 4096 + e];
    if (tid < 64) kss[tid] = ksum[bh * 64 + tid];
    __syncthreads();

    const int warp = tid >> 5, lane = tid & 31;
    const int tpb = LSEQ / gridDim.y;
    const int l0 = blockIdx.y * tpb;

    for (int l = l0 + warp; l < l0 + tpb; l += 8) {
        const float* q = Q + ((size_t)(b * LSEQ + l)) * DMODEL + h * 64;
        const float q0 = q[lane], q1 = q[lane + 32];
        float zd = q0 * kss[lane] + q1 * kss[lane + 32];
        #pragma unroll
        for (int o = 16; o > 0; o >>= 1) zd += __shfl_xor_sync(0xffffffffu, zd, o);
        const float z = 1.f / (zd + 1e-6f);

        float a0 = 0.f, a1 = 0.f;
        #pragma unroll
        for (int dd = 0; dd < 32; dd++) {
            const float qd = __shfl_sync(0xffffffffu, q0, dd);
            a0 = fmaf(qd, kvs[dd][lane],      a0);
            a1 = fmaf(qd, kvs[dd][lane + 32], a1);
        }
        #pragma unroll
        for (int dd = 0; dd < 32; dd++) {
            const float qd = __shfl_sync(0xffffffffu, q1, dd);
            a0 = fmaf(qd, kvs[dd + 32][lane],      a0);
            a1 = fmaf(qd, kvs[dd + 32][lane + 32], a1);
        }
        const size_t op = ((size_t)(b * LSEQ + l)) * DMODEL + h * 64;
        Oh[op + lane]      = __float2half_rn(a0 * z);
        Oh[op + lane + 32] = __float2half_rn(a1 * z);
    }
}

__global__ __launch_bounds__(128) void ln_kernel(
    const float* __restrict__ X, const float* __restrict__ R,
    const float* __restrict__ gb, float* __restrict__ Y,
    fp16* __restrict__ Yh)
{
    const int t = blockIdx.x, tid = threadIdx.x;
    const float* x = X + (size_t)t * DMODEL;
    float v[4];
    float s = 0.f;
    #pragma unroll
    for (int i = 0; i < 4; i++) {
        float val = x[tid + i * 128];
        if (R) val += R[(size_t)t * DMODEL + tid + i * 128];
        v[i] = val; s += val;
    }
    __shared__ float red[4];
    #pragma unroll
    for (int o = 16; o > 0; o >>= 1) s += __shfl_xor_sync(0xffffffffu, s, o);
    if ((tid & 31) == 0) red[tid >> 5] = s;
    __syncthreads();
    const float mu = (red[0] + red[1] + red[2] + red[3]) * (1.f / DMODEL);
    float qq = 0.f;
    #pragma unroll
    for (int i = 0; i < 4; i++) { const float dd = v[i] - mu; qq += dd * dd; }
    #pragma unroll
    for (int o = 16; o > 0; o >>= 1) qq += __shfl_xor_sync(0xffffffffu, qq, o);
    __syncthreads();
    if ((tid & 31) == 0) red[tid >> 5] = qq;
    __syncthreads();
    const float var = (red[0] + red[1] + red[2] + red[3]) * (1.f / DMODEL);
    const float rstd = rsqrtf(var + 1e-5f);
    #pragma unroll
    for (int i = 0; i < 4; i++) {
        const int j = tid + i * 128;
        const float out = (v[i] - mu) * rstd * gb[j] + gb[DMODEL + j];
        Y[(size_t)t * DMODEL + j] = out;
        if (Yh) Yh[(size_t)t * DMODEL + j] = __float2half_rn(out);
    }
}

__global__ void embed_kernel(
    const float* __restrict__ x, const float* __restrict__ pe,
    const float* __restrict__ ew, const float* __restrict__ eb,
    float* __restrict__ h, fp16* __restrict__ hh)
{
    const size_t idx = (size_t)blockIdx.x * blockDim.x + threadIdx.x;
    const int tok = (int)(idx >> 9);
    const int j   = (int)(idx & 511);
    const int l   = tok & (LSEQ - 1);
    float val;
    if (j < 256) val = x[(size_t)tok * 2] * ew[j] + x[(size_t)tok * 2 + 1] * ew[256 + j] + eb[j];
    else         val = pe[(size_t)l * 256 + (j - 256)];
    h[idx] = val;
    hh[idx] = __float2half_rn(val);
}

__global__ void dec_init_kernel(const float* __restrict__ ope, float* __restrict__ o,
                                fp16* __restrict__ oh)
{
    const size_t idx = (size_t)blockIdx.x * blockDim.x + threadIdx.x;
    const size_t tok = idx >> 9;
    const float val = ope[((tok & (LSEQ - 1)) << 9) | (idx & 511)];
    o[idx] = val;
    oh[idx] = __float2half_rn(val);
}

__global__ void pred_kernel(
    const float* __restrict__ Xf, const float* __restrict__ pw,
    const float* __restrict__ pb, float* __restrict__ out)
{
    const int gw = (int)(((size_t)blockIdx.x * blockDim.x + threadIdx.x) >> 5);
    const int lane = threadIdx.x & 31;
    if (gw >= NTOK) return;
    const float* xr = Xf + (size_t)gw * DMODEL;
    float a0 = 0.f, a1 = 0.f;
    #pragma unroll 4
    for (int j = lane; j < DMODEL; j += 32) {
        const float v = xr[j];
        a0 = fmaf(v, pw[2 * j],     a0);
        a1 = fmaf(v, pw[2 * j + 1], a1);
    }
    #pragma unroll
    for (int o = 16; o > 0; o >>= 1) {
        a0 += __shfl_xor_sync(0xffffffffu, a0, o);
        a1 += __shfl_xor_sync(0xffffffffu, a1, o);
    }
    if (lane == 0) { out[2 * gw] = a0 + pb[0]; out[2 * gw + 1] = a1 + pb[1]; }
}

// ---------------------------------------------------------------------------
// Host orchestration
// ---------------------------------------------------------------------------
struct Ptrs {
    float *h, *z, *o, *tmp, *q, *k, *v, *pkv, *pks, *kv, *ks;
    fp16 *hh, *zh, *oh, *ath, *fh;
    fp16 *wha, *wla, *whf1, *wlf1, *whf2, *wlf2;
};

static void gemm20(const fp16* a, const fp16* bh, const fp16* bl,
                   const float* bias, float* C, int M, int N, int K) {
    gemm_tc<2,0><<<dim3(N/128, M/128), 256, SMEM_DYN>>>(a, bh, bl, bias, C, nullptr, M, N, K);
}
static void gemm00(const fp16* a, const fp16* bh, const fp16* bl,
                   const float* bias, float* C, int M, int N, int K) {
    gemm_tc<0,0><<<dim3(N/128, M/128), 256, SMEM_DYN>>>(a, bh, bl, bias, C, nullptr, M, N, K);
}
static void gemm11(const fp16* a, const fp16* bh, const fp16* bl,
                   const float* bias, fp16* Ch, int M, int N, int K) {
    gemm_tc<1,1><<<dim3(N/128, M/128), 256, SMEM_DYN>>>(a, bh, bl, bias, nullptr, Ch, M, N, K);
}

static void attention_block(const fp16* xqh, const fp16* xkh,
                            const fp16* wh, const fp16* wl,
                            const float* b, const Ptrs& P)
{
    const size_t WS = (size_t)DMODEL * DMODEL;
    gemm20(xqh, wh + 0 * WS, wl + 0 * WS, b + 0 * DMODEL, P.q, NTOK, DMODEL, DMODEL);
    gemm20(xkh, wh + 1 * WS, wl + 1 * WS, b + 1 * DMODEL, P.k, NTOK, DMODEL, DMODEL);
    gemm00(xkh, wh + 2 * WS, wl + 2 * WS, b + 2 * DMODEL, P.v, NTOK, DMODEL, DMODEL);

    kv_partial<<<dim3(32, SCH), 256>>>(P.k, P.v, P.pkv, P.pks);
    kv_reduce<<<32, 256>>>(P.pkv, P.pks, P.kv, P.ks);
    attn_out<<<dim3(32, 32), 256>>>(P.q, P.kv, P.ks, P.ath);

    gemm00(P.ath, wh + 3 * WS, wl + 3 * WS, b + 3 * DMODEL, P.tmp, NTOK, DMODEL, DMODEL);
}

extern "C" void kernel_launch(void* const* d_in, const int* in_sizes, int n_in,
                              void* d_out, int out_size)
{
    const float* x            = (const float*)d_in[0];
    const float* out_pos_emb  = (const float*)d_in[1];
    const float* pe_input     = (const float*)d_in[2];
    const float* emb_w        = (const float*)d_in[3];
    const float* emb_b        = (const float*)d_in[4];
    const float* enc_attn_w   = (const float*)d_in[5];
    const float* enc_attn_b   = (const float*)d_in[6];
    const float* enc_ln       = (const float*)d_in[7];
    const float* enc_ff_w1    = (const float*)d_in[8];
    const float* enc_ff_b1    = (const float*)d_in[9];
    const float* enc_ff_w2    = (const float*)d_in[10];
    const float* enc_ff_b2    = (const float*)d_in[11];
    const float* enc_final_ln = (const float*)d_in[12];
    const float* dec_self_w   = (const float*)d_in[13];
    const float* dec_self_b   = (const float*)d_in[14];
    const float* dec_cross_w  = (const float*)d_in[15];
    const float* dec_cross_b  = (const float*)d_in[16];
    const float* dec_ln       = (const float*)d_in[17];
    const float* dec_ff_w1    = (const float*)d_in[18];
    const float* dec_ff_b1    = (const float*)d_in[19];
    const float* dec_ff_w2    = (const float*)d_in[20];
    const float* dec_ff_b2    = (const float*)d_in[21];
    const float* dec_final_ln = (const float*)d_in[22];
    const float* pred_w       = (const float*)d_in[23];
    const float* pred_b       = (const float*)d_in[24];

    cudaFuncSetAttribute(gemm_tc<2,0>, cudaFuncAttributeMaxDynamicSharedMemorySize, SMEM_DYN);
    cudaFuncSetAttribute(gemm_tc<0,0>, cudaFuncAttributeMaxDynamicSharedMemorySize, SMEM_DYN);
    cudaFuncSetAttribute(gemm_tc<1,1>, cudaFuncAttributeMaxDynamicSharedMemorySize, SMEM_DYN);

    unsigned char* S = nullptr;
    cudaGetSymbolAddress((void**)&S, g_scratch);

    Ptrs P;
    P.h   = (float*)(S + B_H);   P.z   = (float*)(S + B_Z);   P.o  = (float*)(S + B_O);
    P.tmp = (float*)(S + B_TMP); P.q   = (float*)(S + B_Q);   P.k  = (float*)(S + B_K);
    P.v   = (float*)(S + B_V);   P.pkv = (float*)(S + B_PKV); P.pks = (float*)(S + B_PKS);
    P.kv  = (float*)(S + B_KVB); P.ks  = (float*)(S + B_KSB);
    P.hh  = (fp16*)(S + B_HH);   P.zh  = (fp16*)(S + B_ZH);
    P.oh  = (fp16*)(S + B_OH);   P.ath = (fp16*)(S + B_ATH);
    P.fh  = (fp16*)(S + B_FH);
    P.wha = (fp16*)(S + B_WHA);  P.wla = (fp16*)(S + B_WLA);
    P.whf1 = (fp16*)(S + B_WHF1); P.wlf1 = (fp16*)(S + B_WLF1);
    P.whf2 = (fp16*)(S + B_WHF2); P.wlf2 = (fp16*)(S + B_WLF2);

    // ---- transpose + split all weights ----
    transpose_split_w<<<dim3(16, 16, 16), 256>>>(enc_attn_w,  P.wha,                     P.wla,                     512, 512);
    transpose_split_w<<<dim3(16, 16, 16), 256>>>(dec_self_w,  P.wha + (size_t)16*262144, P.wla + (size_t)16*262144, 512, 512);
    transpose_split_w<<<dim3(16, 16, 16), 256>>>(dec_cross_w, P.wha + (size_t)32*262144, P.wla + (size_t)32*262144, 512, 512);
    transpose_split_w<<<dim3(64, 16, 4),  256>>>(enc_ff_w1, P.whf1,                      P.wlf1,                      512, 2048);
    transpose_split_w<<<dim3(64, 16, 4),  256>>>(dec_ff_w1, P.whf1 + (size_t)4*1048576,  P.wlf1 + (size_t)4*1048576,  512, 2048);
    transpose_split_w<<<dim3(16, 64, 4),  256>>>(enc_ff_w2, P.whf2,                      P.wlf2,                      2048, 512);
    transpose_split_w<<<dim3(16, 64, 4),  256>>>(dec_ff_w2, P.whf2 + (size_t)4*1048576,  P.wlf2 + (size_t)4*1048576,  2048, 512);

    const size_t WT4 = (size_t)4 * DMODEL * DMODEL;
    const size_t W1S = (size_t)DFF * DMODEL;
    const size_t W2S = (size_t)DMODEL * DFF;

    // ---- embed ----
    embed_kernel<<<(NTOK * DMODEL) / 256, 256>>>(x, pe_input, emb_w, emb_b, P.h, P.hh);

    // ---- encoder ----
    for (int l = 0; l < 4; l++) {
        const float* ln = enc_ln + (size_t)l * 2 * 2 * DMODEL;
        attention_block(P.hh, P.hh,
                        P.wha + (size_t)l * WT4, P.wla + (size_t)l * WT4,
                        enc_attn_b + (size_t)l * 4 * DMODEL, P);
        ln_kernel<<<NTOK, 128>>>(P.h, P.tmp, ln, P.h, P.hh);
        gemm11(P.hh, P.whf1 + (size_t)l * W1S, P.wlf1 + (size_t)l * W1S,
               enc_ff_b1 + (size_t)l * DFF, P.fh, NTOK, DFF, DMODEL);
        gemm00(P.fh, P.whf2 + (size_t)l * W2S, P.wlf2 + (size_t)l * W2S,
               enc_ff_b2 + (size_t)l * DMODEL, P.tmp, NTOK, DMODEL, DFF);
        ln_kernel<<<NTOK, 128>>>(P.h, P.tmp, ln + 2 * DMODEL, P.h, P.hh);
    }
    ln_kernel<<<NTOK, 128>>>(P.h, nullptr, enc_final_ln, P.z, P.zh);

    // ---- decoder ----
    dec_init_kernel<<<(NTOK * DMODEL) / 256, 256>>>(out_pos_emb, P.o, P.oh);
    for (int l = 0; l < 4; l++) {
        const float* ln = dec_ln + (size_t)l * 3 * 2 * DMODEL;
        attention_block(P.oh, P.oh,
                        P.wha + (size_t)(16 + l * 4) * DMODEL * DMODEL,
                        P.wla + (size_t)(16 + l * 4) * DMODEL * DMODEL,
                        dec_self_b + (size_t)l * 4 * DMODEL, P);
        ln_kernel<<<NTOK, 128>>>(P.o, P.tmp, ln, P.o, P.oh);
        attention_block(P.oh, P.zh,
                        P.wha + (size_t)(32 + l * 4) * DMODEL * DMODEL,
                        P.wla + (size_t)(32 + l * 4) * DMODEL * DMODEL,
                        dec_cross_b + (size_t)l * 4 * DMODEL, P);
        ln_kernel<<<NTOK, 128>>>(P.o, P.tmp, ln + 2 * DMODEL, P.o, P.oh);
        gemm11(P.oh, P.whf1 + (size_t)(4 + l) * W1S, P.wlf1 + (size_t)(4 + l) * W1S,
               dec_ff_b1 + (size_t)l * DFF, P.fh, NTOK, DFF, DMODEL);
        gemm00(P.fh, P.whf2 + (size_t)(4 + l) * W2S, P.wlf2 + (size_t)(4 + l) * W2S,
               dec_ff_b2 + (size_t)l * DMODEL, P.tmp, NTOK, DMODEL, DFF);
        ln_kernel<<<NTOK, 128>>>(P.o, P.tmp, ln + 4 * DMODEL, P.o, P.oh);
    }
    ln_kernel<<<NTOK, 128>>>(P.o, nullptr, dec_final_ln, P.tmp, nullptr);

    // ---- prediction head ----
    pred_kernel<<<(NTOK * 32) / 256, 256>>>(P.tmp, pred_w, pred_b, (float*)d_out);
}

// round 7
// speedup vs baseline: 1.9363x; 1.3170x over previous
#include <cuda_runtime.h>
#include <cuda_fp16.h>
#include <cstdint>
#include <cstddef>

// ---------------------------------------------------------------------------
// TRecTransformer: linear-attention encoder/decoder.
// GEMMs: plain fp16 mma.sync m16n8k16 (fp32 accum), both operands
// single-rounded fp16, cp.async 3-stage pipeline.
// ---------------------------------------------------------------------------

#define NTOK   16384
#define DMODEL 512
#define DFF    2048
#define LSEQ   4096
#define SCH    16

#define SZ ((size_t)NTOK * DMODEL)        // 8,388,608 elements

// ---- scratch layout (BYTE offsets) ----
#define B_H     ((size_t)0)
#define B_Z     (B_H   + SZ*4)
#define B_O     (B_Z   + SZ*4)
#define B_TMP   (B_O   + SZ*4)
#define B_Q     (B_TMP + SZ*4)
#define B_K     (B_Q   + SZ*4)
#define B_V     (B_K   + SZ*4)
#define B_PKV   (B_V   + SZ*4)
#define B_PKS   (B_PKV + (size_t)SCH*32*4096*4)
#define B_KVB   (B_PKS + (size_t)SCH*32*64*4)
#define B_KSB   (B_KVB + (size_t)32*4096*4)
// fp16 activations (single-rounded)
#define B_HH    (B_KSB + (size_t)32*64*4)
#define B_ZH    (B_HH  + SZ*2)
#define B_OH    (B_ZH  + SZ*2)
#define B_ATH   (B_OH  + SZ*2)
#define B_FH    (B_ATH + SZ*2)            // NTOK*DFF halves
// fp16 weights (single-rounded, transposed to [N,K])
#define B_WHA   (B_FH  + SZ*8)            // 48 x 512x512
#define B_WHF1  (B_WHA + (size_t)48*262144*2)   // 8 x [2048,512]
#define B_WHF2  (B_WHF1 + (size_t)8*1048576*2)  // 8 x [512,2048]
#define TOTAL_B (B_WHF2 + (size_t)8*1048576*2)

__device__ __align__(1024) unsigned char g_scratch[TOTAL_B];

typedef __half fp16;

// ---------------------------------------------------------------------------
// helpers
// ---------------------------------------------------------------------------
__device__ __forceinline__ uint32_t smem_u32(const void* p) {
    uint32_t a;
    asm("{ .reg .u64 t; cvta.to.shared.u64 t, %1; cvt.u32.u64 %0, t; }" : "=r"(a) : "l"(p));
    return a;
}
__device__ __forceinline__ void ldsm4(uint32_t* r, uint32_t addr) {
    asm volatile("ldmatrix.sync.aligned.m8n8.x4.shared.b16 {%0,%1,%2,%3}, [%4];"
        : "=r"(r[0]), "=r"(r[1]), "=r"(r[2]), "=r"(r[3]) : "r"(addr));
}
__device__ __forceinline__ void mma_f16(float* c, const uint32_t* a, const uint32_t* b) {
    asm volatile(
        "mma.sync.aligned.m16n8k16.row.col.f32.f16.f16.f32 "
        "{%0,%1,%2,%3}, {%4,%5,%6,%7}, {%8,%9}, {%0,%1,%2,%3};"
        : "+f"(c[0]), "+f"(c[1]), "+f"(c[2]), "+f"(c[3])
        : "r"(a[0]), "r"(a[1]), "r"(a[2]), "r"(a[3]), "r"(b[0]), "r"(b[1]));
}
__device__ __forceinline__ void cp16(uint32_t d, const void* s) {
    asm volatile("cp.async.cg.shared.global [%0], [%1], 16;" :: "r"(d), "l"(s));
}
__device__ __forceinline__ void cp_commit() { asm volatile("cp.async.commit_group;" ::: "memory"); }
__device__ __forceinline__ void cp_wait1()  { asm volatile("cp.async.wait_group 1;" ::: "memory"); }
__device__ __forceinline__ void cp_wait0()  { asm volatile("cp.async.wait_group 0;" ::: "memory"); }

// ---------------------------------------------------------------------------
// GEMM: C[M,N] = act(A[M,K] @ W[N,K]^T + bias). fp16 mma.sync, fp32 accum.
// 128x128 tile, Kc=32, 256 threads, 3-stage cp.async pipeline,
// 2 smem matrices per stage (A, W).
// ACT: 0 none, 1 relu, 2 phi=elu+1.  OUTBF: 0 -> fp32 C, 1 -> fp16 Ch.
// ---------------------------------------------------------------------------
#define ROWB 80
#define MATB 10240
#define STGB 20480
#define SMEM_DYN (3 * STGB)

template<int ACT, int OUTBF>
__global__ __launch_bounds__(256) void gemm_tc(
    const fp16* __restrict__ A, const fp16* __restrict__ B,
    const float* __restrict__ bias,
    float* __restrict__ C, fp16* __restrict__ Ch,
    int M, int N, int K)
{
    extern __shared__ char smc[];
    const uint32_t smB = smem_u32(smc);

    const int tid = threadIdx.x, lane = tid & 31, wid = tid >> 5;
    const int row0 = blockIdx.y * 128, col0 = blockIdx.x * 128;
    const int wm = wid & 1, wn = wid >> 1;       // 2 x 4 warp grid

    float acc[4][4][4];
    #pragma unroll
    for (int i = 0; i < 4; i++)
        #pragma unroll
        for (int j = 0; j < 4; j++)
            #pragma unroll
            for (int e = 0; e < 4; e++) acc[i][j][e] = 0.f;

    const uint32_t aoff = (uint32_t)((wm * 64 + (lane & 7) + ((lane >> 3) & 1) * 8) * ROWB
                                     + (lane >> 4) * 16);
    const uint32_t boff = (uint32_t)((wn * 32 + (lane >> 4) * 8 + (lane & 7)) * ROWB
                                     + ((lane >> 3) & 1) * 16);

    const int NC = K / 32;
    const int pr = tid >> 2;             // producer row within 64-row half
    const int pb = (tid & 3) * 16;       // byte offset within 64B row chunk

    auto loadst = [&](int c, int s) {
        const int k0 = c * 32;
        const uint32_t st = smB + (uint32_t)s * STGB;
        #pragma unroll
        for (int m = 0; m < 2; m++) {
            const fp16* g = (m == 0) ? A : B;
            const int rb = (m == 0) ? row0 : col0;
            #pragma unroll
            for (int hf = 0; hf < 2; hf++) {
                const int r = hf * 64 + pr;
                cp16(st + m * MATB + r * ROWB + pb,
                     (const char*)(g + (size_t)(rb + r) * K + k0) + pb);
            }
        }
    };

    auto compute = [&](int s) {
        const uint32_t base = smB + (uint32_t)s * STGB;
        #pragma unroll
        for (int ks = 0; ks < 2; ks++) {
            uint32_t ar[4][4], br[4][2];
            #pragma unroll
            for (int mi = 0; mi < 4; mi++)
                ldsm4(ar[mi], base + aoff + mi * 1280 + ks * 32);
            #pragma unroll
            for (int j = 0; j < 2; j++) {
                uint32_t t[4];
                ldsm4(t, base + MATB + boff + j * 1280 + ks * 32);
                br[2 * j][0] = t[0]; br[2 * j][1] = t[1];
                br[2 * j + 1][0] = t[2]; br[2 * j + 1][1] = t[3];
            }
            #pragma unroll
            for (int mi = 0; mi < 4; mi++)
                #pragma unroll
                for (int ni = 0; ni < 4; ni++) mma_f16(acc[mi][ni], ar[mi], br[ni]);
        }
    };

    loadst(0, 0); cp_commit();
    loadst(1, 1); cp_commit();
    for (int c = 0; c < NC; c++) {
        if (c + 1 < NC) cp_wait1(); else cp_wait0();
        __syncthreads();
        compute(c % 3);
        if (c + 2 < NC) { loadst(c + 2, (c + 2) % 3); cp_commit(); }
    }

    // epilogue
    const int gm0 = row0 + wm * 64;
    const int gn0 = col0 + wn * 32;
    #pragma unroll
    for (int ni = 0; ni < 4; ni++) {
        const int cn = gn0 + ni * 8 + (lane & 3) * 2;
        const float b0 = bias[cn], b1 = bias[cn + 1];
        #pragma unroll
        for (int mi = 0; mi < 4; mi++) {
            const int rm = gm0 + mi * 16 + (lane >> 2);
            float t0 = acc[mi][ni][0] + b0;
            float t1 = acc[mi][ni][1] + b1;
            float t2 = acc[mi][ni][2] + b0;
            float t3 = acc[mi][ni][3] + b1;
            if (ACT == 1) {
                t0 = fmaxf(t0, 0.f); t1 = fmaxf(t1, 0.f);
                t2 = fmaxf(t2, 0.f); t3 = fmaxf(t3, 0.f);
            }
            if (ACT == 2) {
                t0 = t0 > 0.f ? t0 + 1.f : __expf(t0);
                t1 = t1 > 0.f ? t1 + 1.f : __expf(t1);
                t2 = t2 > 0.f ? t2 + 1.f : __expf(t2);
                t3 = t3 > 0.f ? t3 + 1.f : __expf(t3);
            }
            if (OUTBF == 0) {
                float2 v0; v0.x = t0; v0.y = t1;
                float2 v1; v1.x = t2; v1.y = t3;
                *(float2*)&C[(size_t)rm * N + cn]       = v0;
                *(float2*)&C[(size_t)(rm + 8) * N + cn] = v1;
            } else {
                __half2 hp;
                hp.x = __float2half_rn(t0); hp.y = __float2half_rn(t1);
                *(__half2*)&Ch[(size_t)rm * N + cn] = hp;
                hp.x = __float2half_rn(t2); hp.y = __float2half_rn(t3);
                *(__half2*)&Ch[(size_t)(rm + 8) * N + cn] = hp;
            }
        }
    }
}

// ---------------------------------------------------------------------------
// fused weight transpose + fp16 round: W[K,N] fp32 -> Wh [N,K] fp16
// ---------------------------------------------------------------------------
__global__ __launch_bounds__(256) void transpose_w16(
    const float* __restrict__ W, fp16* __restrict__ Wh, int K, int N)
{
    __shared__ float t[32][33];
    const size_t mo = (size_t)blockIdx.z * K * N;
    const float* Wm = W + mo;
    const int n0 = blockIdx.x * 32, k0 = blockIdx.y * 32;
    const int tx = threadIdx.x & 31, ty = threadIdx.x >> 5;
    #pragma unroll
    for (int i = 0; i < 32; i += 8)
        t[ty + i][tx] = Wm[(size_t)(k0 + ty + i) * N + n0 + tx];
    __syncthreads();
    #pragma unroll
    for (int i = 0; i < 32; i += 8)
        Wh[mo + (size_t)(n0 + ty + i) * K + k0 + tx] = __float2half_rn(t[tx][ty + i]);
}

// ---------------------------------------------------------------------------
// linear-attention kernels
// ---------------------------------------------------------------------------
__global__ __launch_bounds__(256) void kv_partial(
    const float* __restrict__ Kt, const float* __restrict__ Vt,
    float* __restrict__ pkv, float* __restrict__ pks)
{
    const int bh = blockIdx.x, ch = blockIdx.y;
    const int b = bh >> 3, h = bh & 7;
    const int tid = threadIdx.x;
    __shared__ float Ks[4][64], Vs[4][64];

    float acc[16];
    #pragma unroll
    for (int j = 0; j < 16; j++) acc[j] = 0.f;
    float ksa = 0.f;

    const int s0 = ch * (LSEQ / SCH);
    const size_t base = ((size_t)b * LSEQ) * DMODEL + h * 64;
    const int r = tid >> 6, d = tid & 63;

    for (int s = s0; s < s0 + LSEQ / SCH; s += 4) {
        const size_t off = base + (size_t)(s + r) * DMODEL + d;
        Ks[r][d] = Kt[off];
        Vs[r][d] = Vt[off];
        __syncthreads();
        #pragma unroll
        for (int rr = 0; rr < 4; rr++) {
            #pragma unroll
            for (int j = 0; j < 16; j++) {
                const int flat = j * 256 + tid;
                acc[j] = fmaf(Ks[rr][flat >> 6], Vs[rr][flat & 63], acc[j]);
            }
            if (tid < 64) ksa += Ks[rr][tid];
        }
        __syncthreads();
    }
    float* o = pkv + ((size_t)ch * 32 + bh) * 4096;
    #pragma unroll
    for (int j = 0; j < 16; j++) o[j * 256 + tid] = acc[j];
    if (tid < 64) pks[((size_t)ch * 32 + bh) * 64 + tid] = ksa;
}

__global__ __launch_bounds__(256) void kv_reduce(
    const float* __restrict__ pkv, const float* __restrict__ pks,
    float* __restrict__ kv, float* __restrict__ ks)
{
    const int bh = blockIdx.x, tid = threadIdx.x;
    for (int e = tid; e < 4096; e += 256) {
        float s = 0.f;
        #pragma unroll
        for (int c = 0; c < SCH; c++) s += pkv[((size_t)c * 32 + bh) * 4096 + e];
        kv[(size_t)bh * 4096 + e] = s;
    }
    if (tid < 64) {
        float s = 0.f;
        #pragma unroll
        for (int c = 0; c < SCH; c++) s += pks[((size_t)c * 32 + bh) * 64 + tid];
        ks[bh * 64 + tid] = s;
    }
}

__global__ __launch_bounds__(256) void attn_out(
    const float* __restrict__ Q, const float* __restrict__ kv,
    const float* __restrict__ ksum, fp16* __restrict__ Oh)
{
    const int bh = blockIdx.x, b = bh >> 3, h = bh & 7;
    __shared__ float kvs[64][64];
    __shared__ float kss[64];
    const int tid = threadIdx.x;
    for (int e = tid; e < 4096; e += 256) kvs[e >> 6][e & 63] = kv[(size_t)bh * 4096 + e];
    if (tid < 64) kss[tid] = ksum[bh * 64 + tid];
    __syncthreads();

    const int warp = tid >> 5, lane = tid & 31;
    const int tpb = LSEQ / gridDim.y;
    const int l0 = blockIdx.y * tpb;

    for (int l = l0 + warp; l < l0 + tpb; l += 8) {
        const float* q = Q + ((size_t)(b * LSEQ + l)) * DMODEL + h * 64;
        const float q0 = q[lane], q1 = q[lane + 32];
        float zd = q0 * kss[lane] + q1 * kss[lane + 32];
        #pragma unroll
        for (int o = 16; o > 0; o >>= 1) zd += __shfl_xor_sync(0xffffffffu, zd, o);
        const float z = 1.f / (zd + 1e-6f);

        float a0 = 0.f, a1 = 0.f;
        #pragma unroll
        for (int dd = 0; dd < 32; dd++) {
            const float qd = __shfl_sync(0xffffffffu, q0, dd);
            a0 = fmaf(qd, kvs[dd][lane],      a0);
            a1 = fmaf(qd, kvs[dd][lane + 32], a1);
        }
        #pragma unroll
        for (int dd = 0; dd < 32; dd++) {
            const float qd = __shfl_sync(0xffffffffu, q1, dd);
            a0 = fmaf(qd, kvs[dd + 32][lane],      a0);
            a1 = fmaf(qd, kvs[dd + 32][lane + 32], a1);
        }
        const size_t op = ((size_t)(b * LSEQ + l)) * DMODEL + h * 64;
        Oh[op + lane]      = __float2half_rn(a0 * z);
        Oh[op + lane + 32] = __float2half_rn(a1 * z);
    }
}

__global__ __launch_bounds__(128) void ln_kernel(
    const float* __restrict__ X, const float* __restrict__ R,
    const float* __restrict__ gb, float* __restrict__ Y,
    fp16* __restrict__ Yh)
{
    const int t = blockIdx.x, tid = threadIdx.x;
    const float* x = X + (size_t)t * DMODEL;
    float v[4];
    float s = 0.f;
    #pragma unroll
    for (int i = 0; i < 4; i++) {
        float val = x[tid + i * 128];
        if (R) val += R[(size_t)t * DMODEL + tid + i * 128];
        v[i] = val; s += val;
    }
    __shared__ float red[4];
    #pragma unroll
    for (int o = 16; o > 0; o >>= 1) s += __shfl_xor_sync(0xffffffffu, s, o);
    if ((tid & 31) == 0) red[tid >> 5] = s;
    __syncthreads();
    const float mu = (red[0] + red[1] + red[2] + red[3]) * (1.f / DMODEL);
    float qq = 0.f;
    #pragma unroll
    for (int i = 0; i < 4; i++) { const float dd = v[i] - mu; qq += dd * dd; }
    #pragma unroll
    for (int o = 16; o > 0; o >>= 1) qq += __shfl_xor_sync(0xffffffffu, qq, o);
    __syncthreads();
    if ((tid & 31) == 0) red[tid >> 5] = qq;
    __syncthreads();
    const float var = (red[0] + red[1] + red[2] + red[3]) * (1.f / DMODEL);
    const float rstd = rsqrtf(var + 1e-5f);
    #pragma unroll
    for (int i = 0; i < 4; i++) {
        const int j = tid + i * 128;
        const float out = (v[i] - mu) * rstd * gb[j] + gb[DMODEL + j];
        Y[(size_t)t * DMODEL + j] = out;
        if (Yh) Yh[(size_t)t * DMODEL + j] = __float2half_rn(out);
    }
}

__global__ void embed_kernel(
    const float* __restrict__ x, const float* __restrict__ pe,
    const float* __restrict__ ew, const float* __restrict__ eb,
    float* __restrict__ h, fp16* __restrict__ hh)
{
    const size_t idx = (size_t)blockIdx.x * blockDim.x + threadIdx.x;
    const int tok = (int)(idx >> 9);
    const int j   = (int)(idx & 511);
    const int l   = tok & (LSEQ - 1);
    float val;
    if (j < 256) val = x[(size_t)tok * 2] * ew[j] + x[(size_t)tok * 2 + 1] * ew[256 + j] + eb[j];
    else         val = pe[(size_t)l * 256 + (j - 256)];
    h[idx] = val;
    hh[idx] = __float2half_rn(val);
}

__global__ void dec_init_kernel(const float* __restrict__ ope, float* __restrict__ o,
                                fp16* __restrict__ oh)
{
    const size_t idx = (size_t)blockIdx.x * blockDim.x + threadIdx.x;
    const size_t tok = idx >> 9;
    const float val = ope[((tok & (LSEQ - 1)) << 9) | (idx & 511)];
    o[idx] = val;
    oh[idx] = __float2half_rn(val);
}

__global__ void pred_kernel(
    const float* __restrict__ Xf, const float* __restrict__ pw,
    const float* __restrict__ pb, float* __restrict__ out)
{
    const int gw = (int)(((size_t)blockIdx.x * blockDim.x + threadIdx.x) >> 5);
    const int lane = threadIdx.x & 31;
    if (gw >= NTOK) return;
    const float* xr = Xf + (size_t)gw * DMODEL;
    float a0 = 0.f, a1 = 0.f;
    #pragma unroll 4
    for (int j = lane; j < DMODEL; j += 32) {
        const float v = xr[j];
        a0 = fmaf(v, pw[2 * j],     a0);
        a1 = fmaf(v, pw[2 * j + 1], a1);
    }
    #pragma unroll
    for (int o = 16; o > 0; o >>= 1) {
        a0 += __shfl_xor_sync(0xffffffffu, a0, o);
        a1 += __shfl_xor_sync(0xffffffffu, a1, o);
    }
    if (lane == 0) { out[2 * gw] = a0 + pb[0]; out[2 * gw + 1] = a1 + pb[1]; }
}

// ---------------------------------------------------------------------------
// Host orchestration
// ---------------------------------------------------------------------------
struct Ptrs {
    float *h, *z, *o, *tmp, *q, *k, *v, *pkv, *pks, *kv, *ks;
    fp16 *hh, *zh, *oh, *ath, *fh;
    fp16 *wha, *whf1, *whf2;
};

static void gemm20(const fp16* a, const fp16* b, const float* bias,
                   float* C, int M, int N, int K) {
    gemm_tc<2,0><<<dim3(N/128, M/128), 256, SMEM_DYN>>>(a, b, bias, C, nullptr, M, N, K);
}
static void gemm00(const fp16* a, const fp16* b, const float* bias,
                   float* C, int M, int N, int K) {
    gemm_tc<0,0><<<dim3(N/128, M/128), 256, SMEM_DYN>>>(a, b, bias, C, nullptr, M, N, K);
}
static void gemm11(const fp16* a, const fp16* b, const float* bias,
                   fp16* Ch, int M, int N, int K) {
    gemm_tc<1,1><<<dim3(N/128, M/128), 256, SMEM_DYN>>>(a, b, bias, nullptr, Ch, M, N, K);
}

static void attention_block(const fp16* xqh, const fp16* xkh,
                            const fp16* wh, const float* b, const Ptrs& P)
{
    const size_t WS = (size_t)DMODEL * DMODEL;
    gemm20(xqh, wh + 0 * WS, b + 0 * DMODEL, P.q, NTOK, DMODEL, DMODEL);
    gemm20(xkh, wh + 1 * WS, b + 1 * DMODEL, P.k, NTOK, DMODEL, DMODEL);
    gemm00(xkh, wh + 2 * WS, b + 2 * DMODEL, P.v, NTOK, DMODEL, DMODEL);

    kv_partial<<<dim3(32, SCH), 256>>>(P.k, P.v, P.pkv, P.pks);
    kv_reduce<<<32, 256>>>(P.pkv, P.pks, P.kv, P.ks);
    attn_out<<<dim3(32, 32), 256>>>(P.q, P.kv, P.ks, P.ath);

    gemm00(P.ath, wh + 3 * WS, b + 3 * DMODEL, P.tmp, NTOK, DMODEL, DMODEL);
}

extern "C" void kernel_launch(void* const* d_in, const int* in_sizes, int n_in,
                              void* d_out, int out_size)
{
    const float* x            = (const float*)d_in[0];
    const float* out_pos_emb  = (const float*)d_in[1];
    const float* pe_input     = (const float*)d_in[2];
    const float* emb_w        = (const float*)d_in[3];
    const float* emb_b        = (const float*)d_in[4];
    const float* enc_attn_w   = (const float*)d_in[5];
    const float* enc_attn_b   = (const float*)d_in[6];
    const float* enc_ln       = (const float*)d_in[7];
    const float* enc_ff_w1    = (const float*)d_in[8];
    const float* enc_ff_b1    = (const float*)d_in[9];
    const float* enc_ff_w2    = (const float*)d_in[10];
    const float* enc_ff_b2    = (const float*)d_in[11];
    const float* enc_final_ln = (const float*)d_in[12];
    const float* dec_self_w   = (const float*)d_in[13];
    const float* dec_self_b   = (const float*)d_in[14];
    const float* dec_cross_w  = (const float*)d_in[15];
    const float* dec_cross_b  = (const float*)d_in[16];
    const float* dec_ln       = (const float*)d_in[17];
    const float* dec_ff_w1    = (const float*)d_in[18];
    const float* dec_ff_b1    = (const float*)d_in[19];
    const float* dec_ff_w2    = (const float*)d_in[20];
    const float* dec_ff_b2    = (const float*)d_in[21];
    const float* dec_final_ln = (const float*)d_in[22];
    const float* pred_w       = (const float*)d_in[23];
    const float* pred_b       = (const float*)d_in[24];

    cudaFuncSetAttribute(gemm_tc<2,0>, cudaFuncAttributeMaxDynamicSharedMemorySize, SMEM_DYN);
    cudaFuncSetAttribute(gemm_tc<0,0>, cudaFuncAttributeMaxDynamicSharedMemorySize, SMEM_DYN);
    cudaFuncSetAttribute(gemm_tc<1,1>, cudaFuncAttributeMaxDynamicSharedMemorySize, SMEM_DYN);

    unsigned char* S = nullptr;
    cudaGetSymbolAddress((void**)&S, g_scratch);

    Ptrs P;
    P.h   = (float*)(S + B_H);   P.z   = (float*)(S + B_Z);   P.o  = (float*)(S + B_O);
    P.tmp = (float*)(S + B_TMP); P.q   = (float*)(S + B_Q);   P.k  = (float*)(S + B_K);
    P.v   = (float*)(S + B_V);   P.pkv = (float*)(S + B_PKV); P.pks = (float*)(S + B_PKS);
    P.kv  = (float*)(S + B_KVB); P.ks  = (float*)(S + B_KSB);
    P.hh  = (fp16*)(S + B_HH);   P.zh  = (fp16*)(S + B_ZH);
    P.oh  = (fp16*)(S + B_OH);   P.ath = (fp16*)(S + B_ATH);
    P.fh  = (fp16*)(S + B_FH);
    P.wha = (fp16*)(S + B_WHA);
    P.whf1 = (fp16*)(S + B_WHF1);
    P.whf2 = (fp16*)(S + B_WHF2);

    // ---- transpose + fp16-round all weights ----
    transpose_w16<<<dim3(16, 16, 16), 256>>>(enc_attn_w,  P.wha,                     512, 512);
    transpose_w16<<<dim3(16, 16, 16), 256>>>(dec_self_w,  P.wha + (size_t)16*262144, 512, 512);
    transpose_w16<<<dim3(16, 16, 16), 256>>>(dec_cross_w, P.wha + (size_t)32*262144, 512, 512);
    transpose_w16<<<dim3(64, 16, 4),  256>>>(enc_ff_w1, P.whf1,                      512, 2048);
    transpose_w16<<<dim3(64, 16, 4),  256>>>(dec_ff_w1, P.whf1 + (size_t)4*1048576,  512, 2048);
    transpose_w16<<<dim3(16, 64, 4),  256>>>(enc_ff_w2, P.whf2,                      2048, 512);
    transpose_w16<<<dim3(16, 64, 4),  256>>>(dec_ff_w2, P.whf2 + (size_t)4*1048576,  2048, 512);

    const size_t WT4 = (size_t)4 * DMODEL * DMODEL;
    const size_t W1S = (size_t)DFF * DMODEL;
    const size_t W2S = (size_t)DMODEL * DFF;

    // ---- embed ----
    embed_kernel<<<(NTOK * DMODEL) / 256, 256>>>(x, pe_input, emb_w, emb_b, P.h, P.hh);

    // ---- encoder ----
    for (int l = 0; l < 4; l++) {
        const float* ln = enc_ln + (size_t)l * 2 * 2 * DMODEL;
        attention_block(P.hh, P.hh, P.wha + (size_t)l * WT4,
                        enc_attn_b + (size_t)l * 4 * DMODEL, P);
        ln_kernel<<<NTOK, 128>>>(P.h, P.tmp, ln, P.h, P.hh);
        gemm11(P.hh, P.whf1 + (size_t)l * W1S,
               enc_ff_b1 + (size_t)l * DFF, P.fh, NTOK, DFF, DMODEL);
        gemm00(P.fh, P.whf2 + (size_t)l * W2S,
               enc_ff_b2 + (size_t)l * DMODEL, P.tmp, NTOK, DMODEL, DFF);
        ln_kernel<<<NTOK, 128>>>(P.h, P.tmp, ln + 2 * DMODEL, P.h, P.hh);
    }
    ln_kernel<<<NTOK, 128>>>(P.h, nullptr, enc_final_ln, P.z, P.zh);

    // ---- decoder ----
    dec_init_kernel<<<(NTOK * DMODEL) / 256, 256>>>(out_pos_emb, P.o, P.oh);
    for (int l = 0; l < 4; l++) {
        const float* ln = dec_ln + (size_t)l * 3 * 2 * DMODEL;
        attention_block(P.oh, P.oh,
                        P.wha + (size_t)(16 + l * 4) * DMODEL * DMODEL,
                        dec_self_b + (size_t)l * 4 * DMODEL, P);
        ln_kernel<<<NTOK, 128>>>(P.o, P.tmp, ln, P.o, P.oh);
        attention_block(P.oh, P.zh,
                        P.wha + (size_t)(32 + l * 4) * DMODEL * DMODEL,
                        dec_cross_b + (size_t)l * 4 * DMODEL, P);
        ln_kernel<<<NTOK, 128>>>(P.o, P.tmp, ln + 2 * DMODEL, P.o, P.oh);
        gemm11(P.oh, P.whf1 + (size_t)(4 + l) * W1S,
               dec_ff_b1 + (size_t)l * DFF, P.fh, NTOK, DFF, DMODEL);
        gemm00(P.fh, P.whf2 + (size_t)(4 + l) * W2S,
               dec_ff_b2 + (size_t)l * DMODEL, P.tmp, NTOK, DMODEL, DFF);
        ln_kernel<<<NTOK, 128>>>(P.o, P.tmp, ln + 4 * DMODEL, P.o, P.oh);
    }
    ln_kernel<<<NTOK, 128>>>(P.o, nullptr, dec_final_ln, P.tmp, nullptr);

    // ---- prediction head ----
    pred_kernel<<<(NTOK * 32) / 256, 256>>>(P.tmp, pred_w, pred_b, (float*)d_out);
}